// round 2
// baseline (speedup 1.0000x reference)
#include <cuda_runtime.h>
#include <cstddef>

#define B 8
#define L 2048
#define H 8
#define D 64
#define BH 64
#define SK 40
#define U  40
#define HD 512
#define SCALE 0.125f
#define NT 8           // probe key tiles (256 rows each)
#define PKT 256        // probe key tile rows
#define QC 256         // probe q-chunk
#define KS 16          // attention key splits
#define AKT 128        // attention key tile

// ---- device scratch ----
__device__ float g_M[BH * L];
__device__ int   g_top[BH * U];
__device__ float g_vmean[BH * D];
__device__ unsigned char g_ent[L * SK];          // k_local per (q, sorted by (tile,s))
__device__ unsigned char g_off[L * (NT + 1)];    // cumulative counts per (q, tile)
__device__ float g_pv[(size_t)BH * KS * 2 * U * D];  // 21 MB partial PV
__device__ float g_ml[BH * KS * U * 2];              // (m, l) per split

// ------------------------------------------------------------------
// Setup: per-q inverted lists of samples bucketed by 256-row key tile,
// stable in s (deterministic fp accumulation order).
// ------------------------------------------------------------------
__global__ void k_build(const int* __restrict__ IS) {
    int q = blockIdx.x * blockDim.x + threadIdx.x;
    if (q >= L) return;
    int idxs[SK];
    int cnt[NT];
    #pragma unroll
    for (int t = 0; t < NT; ++t) cnt[t] = 0;
    #pragma unroll
    for (int s = 0; s < SK; ++s) {
        idxs[s] = IS[q * SK + s];
        cnt[idxs[s] >> 8]++;
    }
    int off[NT + 1];
    off[0] = 0;
    #pragma unroll
    for (int t = 0; t < NT; ++t) off[t + 1] = off[t] + cnt[t];
    #pragma unroll
    for (int t = 0; t <= NT; ++t) g_off[q * (NT + 1) + t] = (unsigned char)off[t];
    int pos[NT];
    #pragma unroll
    for (int t = 0; t < NT; ++t) pos[t] = off[t];
    #pragma unroll
    for (int s = 0; s < SK; ++s) {
        int t = idxs[s] >> 8;
        g_ent[q * SK + pos[t]++] = (unsigned char)(idxs[s] & 255);
    }
}

// ------------------------------------------------------------------
// Probe: M[bh,q] = max_s - mean_s of sampled dots, via smem K tiles.
// Block = (qchunk, bh). 4 lanes per q, 8 q per warp, 4 sub-passes.
// ------------------------------------------------------------------
__global__ __launch_bounds__(256, 2) void k_probe2(const float* __restrict__ Q,
                                                   const float* __restrict__ Kp) {
    extern __shared__ float ksm[];   // PKT x 68
    int bh = blockIdx.y, qc = blockIdx.x;
    int b = bh >> 3, h = bh & 7;
    int t = threadIdx.x, w = t >> 5, lane = t & 31;
    int g = lane >> 2, li = lane & 3;
    unsigned gmask = 0xFu << (g * 4);
    int qbase = qc * QC + w * 32 + g;   // + sub*8

    // Q rows into registers (16 floats per lane per sub-q)
    float4 qv[4][4];
    #pragma unroll
    for (int sub = 0; sub < 4; ++sub) {
        const float4* qr = (const float4*)(Q + (size_t)(b * L + qbase + sub * 8) * HD
                                             + h * D + li * 16);
        #pragma unroll
        for (int j = 0; j < 4; ++j) qv[sub][j] = qr[j];
    }
    float mx[4], sm[4];
    #pragma unroll
    for (int s = 0; s < 4; ++s) { mx[s] = -3.4e38f; sm[s] = 0.f; }

    for (int kt = 0; kt < NT; ++kt) {
        __syncthreads();
        const float4* src = (const float4*)(Kp + (size_t)(b * L + kt * PKT) * HD + h * D);
        for (int i = t; i < PKT * 16; i += 256) {
            int r = i >> 4, dq = i & 15;
            float4 v = src[(size_t)r * (HD / 4) + dq];
            *(float4*)&ksm[r * 68 + dq * 4] = v;
        }
        __syncthreads();

        #pragma unroll
        for (int sub = 0; sub < 4; ++sub) {
            int q  = qbase + sub * 8;
            int o0 = g_off[q * (NT + 1) + kt];
            int c  = g_off[q * (NT + 1) + kt + 1] - o0;
            const unsigned char* ep = g_ent + q * SK + o0;
            for (int e = 0; e < c; ++e) {
                int kl = ep[e];
                const float4* kr = (const float4*)&ksm[kl * 68 + li * 16];
                float4 k0 = kr[0], k1 = kr[1], k2 = kr[2], k3 = kr[3];
                float p = qv[sub][0].x * k0.x;
                p = fmaf(qv[sub][0].y, k0.y, p); p = fmaf(qv[sub][0].z, k0.z, p);
                p = fmaf(qv[sub][0].w, k0.w, p);
                p = fmaf(qv[sub][1].x, k1.x, p); p = fmaf(qv[sub][1].y, k1.y, p);
                p = fmaf(qv[sub][1].z, k1.z, p); p = fmaf(qv[sub][1].w, k1.w, p);
                p = fmaf(qv[sub][2].x, k2.x, p); p = fmaf(qv[sub][2].y, k2.y, p);
                p = fmaf(qv[sub][2].z, k2.z, p); p = fmaf(qv[sub][2].w, k2.w, p);
                p = fmaf(qv[sub][3].x, k3.x, p); p = fmaf(qv[sub][3].y, k3.y, p);
                p = fmaf(qv[sub][3].z, k3.z, p); p = fmaf(qv[sub][3].w, k3.w, p);
                p += __shfl_xor_sync(gmask, p, 1);
                p += __shfl_xor_sync(gmask, p, 2);
                mx[sub] = fmaxf(mx[sub], p);
                sm[sub] += p;
            }
        }
    }
    if (li == 0) {
        #pragma unroll
        for (int sub = 0; sub < 4; ++sub)
            g_M[bh * L + qbase + sub * 8] = mx[sub] - sm[sub] * (1.f / SK);
    }
}

// ------------------------------------------------------------------
// V mean per (b,h,d)
// ------------------------------------------------------------------
__global__ void k_vmean(const float* __restrict__ V) {
    __shared__ float smem[4 * 64];
    int bh = blockIdx.x; int b = bh >> 3, h = bh & 7;
    int d = threadIdx.x & 63, p = threadIdx.x >> 6;
    float s = 0.f;
    for (int l = p; l < L; l += 4)
        s += V[(size_t)(b * L + l) * HD + h * D + d];
    smem[p * 64 + d] = s;
    __syncthreads();
    if (threadIdx.x < 64) {
        float t = smem[threadIdx.x] + smem[64 + threadIdx.x]
                + smem[128 + threadIdx.x] + smem[192 + threadIdx.x];
        g_vmean[bh * 64 + threadIdx.x] = t * (1.f / L);
    }
}

// ------------------------------------------------------------------
// Exact top-40 of M per (b,h), jax tie semantics (ties -> lower index)
// ------------------------------------------------------------------
__global__ void k_topk() {
    __shared__ unsigned long long key[L];
    __shared__ unsigned long long wred[8];
    int bh = blockIdx.x;
    int t = threadIdx.x, lane = t & 31, w = t >> 5;
    for (int i = t; i < L; i += 256) {
        unsigned int bits = __float_as_uint(g_M[bh * L + i]);
        bits = (bits & 0x80000000u) ? ~bits : (bits | 0x80000000u);
        key[i] = ((unsigned long long)bits << 32) | (unsigned int)(L - 1 - i);
    }
    __syncthreads();
    for (int it = 0; it < U; ++it) {
        unsigned long long best = 0ull;
        for (int i = t; i < L; i += 256) {
            unsigned long long v = key[i];
            if (v > best) best = v;
        }
        #pragma unroll
        for (int o = 16; o; o >>= 1) {
            unsigned long long other = __shfl_xor_sync(0xffffffffu, best, o);
            if (other > best) best = other;
        }
        if (lane == 0) wred[w] = best;
        __syncthreads();
        if (t == 0) {
            unsigned long long bb = wred[0];
            #pragma unroll
            for (int i = 1; i < 8; ++i) if (wred[i] > bb) bb = wred[i];
            int pos = (L - 1) - (int)(bb & 0xffffffffu);
            g_top[bh * U + it] = pos;
            key[pos] = 0ull;
        }
        __syncthreads();
    }
}

// ------------------------------------------------------------------
// Fill output with broadcast V-mean
// ------------------------------------------------------------------
__global__ void k_fill(float* __restrict__ out) {
    int i4 = blockIdx.x * blockDim.x + threadIdx.x;
    int linear = i4 * 4;
    int d = linear & 63;
    int h = (linear >> 6) & 7;
    int b = linear >> 20;
    float4 v = *(const float4*)&g_vmean[(b * 8 + h) * 64 + d];
    *(float4*)(out + linear) = v;
}

// ------------------------------------------------------------------
// Fused scores + partial softmax + PV (flash split-K).
// Block = (ks, bh), 128 keys per block.
// ------------------------------------------------------------------
__global__ __launch_bounds__(256, 2) void k_attn(const float* __restrict__ Q,
                                                 const float* __restrict__ Kp,
                                                 const float* __restrict__ V) {
    extern __shared__ float smem[];
    float* Qsm  = smem;            // 40*64  = 2560
    float* KVsm = smem + 2560;     // 128*68 = 8704
    float* Asm  = KVsm + 8704;     // 40*132 = 5280
    int bh = blockIdx.y, ks = blockIdx.x;
    int b = bh >> 3, h = bh & 7;
    int k0 = ks * AKT;
    int t = threadIdx.x;

    for (int i = t; i < U * 16; i += 256) {
        int u = i >> 4, dq = i & 15;
        int qi = g_top[bh * U + u];
        *(float4*)&Qsm[u * 64 + dq * 4] =
            *(const float4*)&Q[(size_t)(b * L + qi) * HD + h * D + dq * 4];
    }
    for (int i = t; i < AKT * 16; i += 256) {
        int r = i >> 4, dq = i & 15;
        *(float4*)&KVsm[r * 68 + dq * 4] =
            *(const float4*)&Kp[(size_t)(b * L + k0 + r) * HD + h * D + dq * 4];
    }
    __syncthreads();

    // scores: thread = (kg 0..63, ug 0..3); k = kg, kg+64; u = ug*10..+9
    {
        int kg = t & 63, ug = t >> 6;
        float acc[10][2];
        #pragma unroll
        for (int i = 0; i < 10; ++i) { acc[i][0] = 0.f; acc[i][1] = 0.f; }
        for (int d = 0; d < 64; d += 4) {
            float4 ka = *(float4*)&KVsm[kg * 68 + d];
            float4 kb = *(float4*)&KVsm[(kg + 64) * 68 + d];
            #pragma unroll
            for (int i = 0; i < 10; ++i) {
                float4 q4 = *(float4*)&Qsm[(ug * 10 + i) * 64 + d];
                acc[i][0] = fmaf(q4.x, ka.x, acc[i][0]);
                acc[i][0] = fmaf(q4.y, ka.y, acc[i][0]);
                acc[i][0] = fmaf(q4.z, ka.z, acc[i][0]);
                acc[i][0] = fmaf(q4.w, ka.w, acc[i][0]);
                acc[i][1] = fmaf(q4.x, kb.x, acc[i][1]);
                acc[i][1] = fmaf(q4.y, kb.y, acc[i][1]);
                acc[i][1] = fmaf(q4.z, kb.z, acc[i][1]);
                acc[i][1] = fmaf(q4.w, kb.w, acc[i][1]);
            }
        }
        #pragma unroll
        for (int i = 0; i < 10; ++i) {
            Asm[(ug * 10 + i) * 132 + kg]      = acc[i][0] * SCALE;
            Asm[(ug * 10 + i) * 132 + kg + 64] = acc[i][1] * SCALE;
        }
    }
    __syncthreads();

    // V -> KVsm (in flight while stats compute); stats per row
    for (int i = t; i < AKT * 16; i += 256) {
        int r = i >> 4, dq = i & 15;
        *(float4*)&KVsm[r * 68 + dq * 4] =
            *(const float4*)&V[(size_t)(b * L + k0 + r) * HD + h * D + dq * 4];
    }
    {
        int w = t >> 5, lane = t & 31;
        #pragma unroll
        for (int rr = 0; rr < 5; ++rr) {
            int u = w * 5 + rr;
            float vals[4], m = -3.4e38f;
            #pragma unroll
            for (int mm = 0; mm < 4; ++mm) {
                vals[mm] = Asm[u * 132 + lane + 32 * mm];
                m = fmaxf(m, vals[mm]);
            }
            #pragma unroll
            for (int o = 16; o; o >>= 1) m = fmaxf(m, __shfl_xor_sync(0xffffffffu, m, o));
            float lsum = 0.f;
            #pragma unroll
            for (int mm = 0; mm < 4; ++mm) {
                float pe = __expf(vals[mm] - m);
                Asm[u * 132 + lane + 32 * mm] = pe;
                lsum += pe;
            }
            #pragma unroll
            for (int o = 16; o; o >>= 1) lsum += __shfl_xor_sync(0xffffffffu, lsum, o);
            if (lane == 0) {
                g_ml[((bh * KS + ks) * U + u) * 2 + 0] = m;
                g_ml[((bh * KS + ks) * U + u) * 2 + 1] = lsum;
            }
        }
    }
    __syncthreads();

    // PV: thread = (kh 0..1, ug2 0..7, dg 0..15); 5u x 4d over 64 k
    {
        int kh = t >> 7, ug2 = (t >> 4) & 7, dg = t & 15;
        int kb = kh * 64;
        float4 o[5];
        #pragma unroll
        for (int i = 0; i < 5; ++i) o[i] = make_float4(0.f, 0.f, 0.f, 0.f);
        for (int k = 0; k < 64; ++k) {
            float4 v = *(float4*)&KVsm[(kb + k) * 68 + dg * 4];
            #pragma unroll
            for (int i = 0; i < 5; ++i) {
                float a = Asm[(ug2 * 5 + i) * 132 + kb + k];
                o[i].x = fmaf(a, v.x, o[i].x);
                o[i].y = fmaf(a, v.y, o[i].y);
                o[i].z = fmaf(a, v.z, o[i].z);
                o[i].w = fmaf(a, v.w, o[i].w);
            }
        }
        #pragma unroll
        for (int i = 0; i < 5; ++i)
            *(float4*)&g_pv[(size_t)(((bh * KS + ks) * 2 + kh) * U + ug2 * 5 + i) * D + dg * 4] = o[i];
    }
}

// ------------------------------------------------------------------
// Combine split-K partials with softmax rescale, scatter to output
// ------------------------------------------------------------------
__global__ void k_final(float* __restrict__ out) {
    int i4 = blockIdx.x * blockDim.x + threadIdx.x;
    if (i4 >= BH * U * 16) return;
    int dq = i4 & 15;
    int u  = (i4 >> 4) % U;
    int bh = i4 / (U * 16);

    float mv[KS], lv[KS], M = -3.4e38f;
    #pragma unroll
    for (int s = 0; s < KS; ++s) {
        mv[s] = g_ml[((bh * KS + s) * U + u) * 2 + 0];
        lv[s] = g_ml[((bh * KS + s) * U + u) * 2 + 1];
        M = fmaxf(M, mv[s]);
    }
    float4 acc = make_float4(0.f, 0.f, 0.f, 0.f);
    float lsum = 0.f;
    #pragma unroll
    for (int s = 0; s < KS; ++s) {
        float wgt = __expf(mv[s] - M);
        lsum += wgt * lv[s];
        float4 p0 = *(const float4*)&g_pv[(size_t)(((bh * KS + s) * 2 + 0) * U + u) * D + dq * 4];
        float4 p1 = *(const float4*)&g_pv[(size_t)(((bh * KS + s) * 2 + 1) * U + u) * D + dq * 4];
        acc.x = fmaf(wgt, p0.x + p1.x, acc.x);
        acc.y = fmaf(wgt, p0.y + p1.y, acc.y);
        acc.z = fmaf(wgt, p0.z + p1.z, acc.z);
        acc.w = fmaf(wgt, p0.w + p1.w, acc.w);
    }
    float inv = 1.f / lsum;
    int q = g_top[bh * U + u];
    int b = bh >> 3, h = bh & 7;
    *(float4*)&out[(size_t)(b * L + q) * HD + h * D + dq * 4] =
        make_float4(acc.x * inv, acc.y * inv, acc.z * inv, acc.w * inv);
}

// ------------------------------------------------------------------
extern "C" void kernel_launch(void* const* d_in, const int* in_sizes, int n_in,
                              void* d_out, int out_size) {
    const float* Q = (const float*)d_in[0];
    const float* K = (const float*)d_in[1];
    const float* V = (const float*)d_in[2];
    const int*  IS = (const int*)d_in[3];
    float* out = (float*)d_out;

    const int smem_probe = PKT * 68 * 4;                       // 69632
    const int smem_attn  = (2560 + 8704 + 5280) * 4;           // 66176
    cudaFuncSetAttribute(k_probe2, cudaFuncAttributeMaxDynamicSharedMemorySize, smem_probe);
    cudaFuncSetAttribute(k_attn,   cudaFuncAttributeMaxDynamicSharedMemorySize, smem_attn);

    k_build <<<(L + 255) / 256, 256>>>(IS);
    k_vmean <<<BH, 256>>>(V);
    k_probe2<<<dim3(L / QC, BH), 256, smem_probe>>>(Q, K);
    k_topk  <<<BH, 256>>>();
    k_fill  <<<(B * L * HD / 4) / 256, 256>>>(out);
    k_attn  <<<dim3(KS, BH), 256, smem_attn>>>(Q, K, V);
    k_final <<<(BH * U * 16 + 255) / 256, 256>>>(out);
}